// round 7
// baseline (speedup 1.0000x reference)
#include <cuda_runtime.h>
#include <math.h>

#define H1 256
#define W1 256
#define HW1 65536
#define EPSF 1e-5f

typedef unsigned long long ull;
typedef unsigned int u32;

__device__ __forceinline__ ull pk2(float a, float b) {
    ull r; asm("mov.b64 %0,{%1,%2};" : "=l"(r) : "f"(a), "f"(b)); return r;
}
__device__ __forceinline__ ull dup2(float a) {
    ull r; asm("mov.b64 %0,{%1,%1};" : "=l"(r) : "f"(a)); return r;
}
__device__ __forceinline__ void fma2(ull& d, ull a, ull b) {
    asm("fma.rn.f32x2 %0,%1,%2,%0;" : "+l"(d) : "l"(a), "l"(b));
}
__device__ __forceinline__ ull sub2(ull a, ull b) {
    ull r; asm("sub.rn.f32x2 %0,%1,%2;" : "=l"(r) : "l"(a), "l"(b)); return r;
}
__device__ __forceinline__ float2 up2(ull u) {
    float2 r; asm("mov.b64 {%0,%1},%2;" : "=f"(r.x), "=f"(r.y) : "l"(u)); return r;
}
__device__ __forceinline__ u32 s2u(const void* p) {
    u32 a; asm("{.reg .u64 t; cvta.to.shared.u64 t, %1; cvt.u32.u64 %0, t;}" : "=r"(a) : "l"(p));
    return a;
}
__device__ __forceinline__ void cp4(u32 dst, const void* src, int sz) {
    asm volatile("cp.async.ca.shared.global [%0], [%1], 4, %2;" :: "r"(dst), "l"(src), "r"(sz));
}
__device__ __forceinline__ void cp16(u32 dst, const void* src) {
    asm volatile("cp.async.cg.shared.global [%0], [%1], 16;" :: "r"(dst), "l"(src));
}
__device__ __forceinline__ void cp_commit() {
    asm volatile("cp.async.commit_group;");
}
template<int N> __device__ __forceinline__ void cp_wait() {
    asm volatile("cp.async.wait_group %0;" :: "n"(N));
}

// ---------------- scratch ----------------
__device__ float g_h[2 * 64 * HW1];                       // planar (offconv)
__device__ float g_h4[2 * 64 * HW1 + 1024];               // [b][c/4][p][4] (sampler) + pad
__device__ float g_off[2 * 8 * HW1];
__device__ float g_outraw[2 * 16 * HW1];
__device__ __align__(16) ull g_woff2[64 * 9 * 6];         // [c][tap(9)][vch-pair(6)]
__device__ float g_osum[12], g_osq[12];
__device__ float g_ssum[8],  g_ssq[8];

// ---------------- prep ----------------
__global__ void prep_kernel(const float* __restrict__ wx, const float* __restrict__ wy) {
    int idx = blockIdx.x * 256 + threadIdx.x;
    if (idx < 12) { g_osum[idx] = 0.f; g_osq[idx] = 0.f; }
    if (idx < 8)  { g_ssum[idx] = 0.f; g_ssq[idx] = 0.f; }
    if (idx < 1024) g_h4[2 * 64 * HW1 + idx] = 0.f;
    if (idx < 3456) {
        int c = idx / 54, rem = idx - c * 54;
        int t = rem / 6, j = rem - t * 6;
        int v0 = 2 * j, v1 = 2 * j + 1;
        float a = (v0 < 6) ? wx[v0 * 576 + c * 9 + t] : wy[(v0 - 2) * 576 + c * 9 + t];
        float b = (v1 < 6) ? wx[v1 * 576 + c * 9 + t] : wy[(v1 - 2) * 576 + c * 9 + t];
        g_woff2[idx] = pk2(a, b);
    }
}

// ---------------- conv1 3x3 s2 pad1 (3->64) + BN + ReLU; dual-layout store ----------------
__global__ void __launch_bounds__(256) conv1_kernel(
        const float* __restrict__ x, const float* __restrict__ w,
        const float* __restrict__ g, const float* __restrict__ bb,
        const float* __restrict__ m, const float* __restrict__ v) {
    __shared__ __align__(16) ull swp[864];
    __shared__ float ssc[64], ssh[64];
    int tid = threadIdx.x;
    for (int i = tid; i < 864; i += 256) {
        int t = i >> 5, op = i & 31;
        swp[i] = pk2(w[(2 * op) * 27 + t], w[(2 * op + 1) * 27 + t]);
    }
    if (tid < 64) {
        float sc = g[tid] * rsqrtf(v[tid] + EPSF);
        ssc[tid] = sc; ssh[tid] = bb[tid] - m[tid] * sc;
    }
    __syncthreads();

    int idx = blockIdx.x * 256 + tid;
    int b = idx >> 16, p = idx & 65535;
    int oy = p >> 8, ox = p & 255;
    const float* xb = x + (size_t)b * 3 * 512 * 512;

    ull pd[27];
    #pragma unroll
    for (int ic = 0; ic < 3; ic++)
        #pragma unroll
        for (int dy = 0; dy < 3; dy++) {
            int iy = 2 * oy - 1 + dy;
            #pragma unroll
            for (int dx = 0; dx < 3; dx++) {
                int ix = 2 * ox - 1 + dx;
                float val = 0.f;
                if (iy >= 0 && ix >= 0) val = xb[(ic * 512 + iy) * 512 + ix];
                pd[ic * 9 + dy * 3 + dx] = dup2(val);
            }
        }

    float* hb = g_h + (size_t)b * 64 * HW1 + p;
    float4* hb4 = (float4*)g_h4 + (size_t)b * 16 * HW1 + p;
    #pragma unroll 1
    for (int half = 0; half < 2; half++) {
        ull acc[16];
        #pragma unroll
        for (int j = 0; j < 16; j++) acc[j] = 0ull;
        #pragma unroll
        for (int t = 0; t < 27; t++)
            #pragma unroll
            for (int j = 0; j < 16; j++)
                fma2(acc[j], pd[t], swp[t * 32 + half * 16 + j]);
        #pragma unroll
        for (int mm = 0; mm < 8; mm++) {
            int oc = (half * 8 + mm) * 4;
            float2 v0 = up2(acc[2 * mm]);
            float2 v1 = up2(acc[2 * mm + 1]);
            float r0 = fmaxf(fmaf(v0.x, ssc[oc],     ssh[oc]),     0.f);
            float r1 = fmaxf(fmaf(v0.y, ssc[oc + 1], ssh[oc + 1]), 0.f);
            float r2 = fmaxf(fmaf(v1.x, ssc[oc + 2], ssh[oc + 2]), 0.f);
            float r3 = fmaxf(fmaf(v1.y, ssc[oc + 3], ssh[oc + 3]), 0.f);
            hb[(size_t)oc * HW1]       = r0;
            hb[(size_t)(oc + 1) * HW1] = r1;
            hb[(size_t)(oc + 2) * HW1] = r2;
            hb[(size_t)(oc + 3) * HW1] = r3;
            hb4[(size_t)(half * 8 + mm) * HW1] = make_float4(r0, r1, r2, r3);
        }
    }
}

// ---------------- offset convs: 16x16 tile, 1px/thread, vch-pair packed ----------------
__global__ void __launch_bounds__(256) offconv_kernel(
        const float* __restrict__ bxp, const float* __restrict__ byp) {
    __shared__ float st[2][2][18 * 19];
    __shared__ __align__(16) ull wsm[2][2][54];
    int tid = threadIdx.x, tx = tid & 15, ty = tid >> 4;
    int b = blockIdx.z;
    int ox0 = blockIdx.x * 16, oy0 = blockIdx.y * 16;

    // fill slots: 2ch x 18x18 = 648 entries
    int fe[3], fsrc[3], fch[3], fsz[3];
    #pragma unroll
    for (int s = 0; s < 3; s++) {
        int i = tid + s * 256;
        int valid = (i < 648);
        int ii = valid ? i : 0;
        int ch = (ii >= 324) ? 1 : 0;
        int j = ii - ch * 324;
        int r = j / 18, cc = j - r * 18;
        int gy = oy0 - 1 + r, gx = ox0 - 1 + cc;
        int ok = valid && gy >= 0 && gy < H1 && gx >= 0 && gx < W1;
        fe[s] = ch * 342 + r * 19 + cc;
        fch[s] = ch;
        fsrc[s] = min(max(gy, 0), 255) * W1 + min(max(gx, 0), 255);
        fsz[s] = valid ? (ok ? 4 : 0) : -1;
    }
    u32 st0 = s2u(&st[0][0][0]), st1 = s2u(&st[1][0][0]);
    u32 ws0 = s2u(&wsm[0][0][0]), ws1 = s2u(&wsm[1][0][0]);
    const float* hb = g_h + (size_t)b * 64 * HW1;
    const char* wgp = (const char*)g_woff2;

    ull acc[6];
    #pragma unroll
    for (int j = 0; j < 6; j++) {
        int v0 = 2 * j, v1 = 2 * j + 1;
        float a = (v0 < 6) ? bxp[v0] : byp[v0 - 2];
        float c = (v1 < 6) ? bxp[v1] : byp[v1 - 2];
        acc[j] = pk2(a, c);
    }

    {
        #pragma unroll
        for (int s = 0; s < 3; s++)
            if (fsz[s] >= 0) cp4(st0 + fe[s] * 4, hb + (size_t)fch[s] * HW1 + fsrc[s], fsz[s]);
        if (tid < 54) {
            int ch = tid >= 27 ? 1 : 0, o = tid - ch * 27;
            cp16(ws0 + (ch * 54 + o * 2) * 8, wgp + ((size_t)ch * 27 + o) * 16);
        }
        cp_commit();
    }

    #pragma unroll 1
    for (int sg = 0; sg < 32; sg++) {
        int buf = sg & 1;
        if (sg + 1 < 32) {
            u32 std = buf ? st0 : st1;
            u32 wsd = buf ? ws0 : ws1;
            int cbase = 2 * (sg + 1);
            #pragma unroll
            for (int s = 0; s < 3; s++)
                if (fsz[s] >= 0) cp4(std + fe[s] * 4, hb + (size_t)(cbase + fch[s]) * HW1 + fsrc[s], fsz[s]);
            if (tid < 54) {
                int ch = tid >= 27 ? 1 : 0, o = tid - ch * 27;
                cp16(wsd + (ch * 54 + o * 2) * 8, wgp + ((size_t)(cbase + ch) * 27 + o) * 16);
            }
            cp_commit();
            cp_wait<1>();
        } else {
            cp_wait<0>();
        }
        __syncthreads();

        #pragma unroll
        for (int cc2 = 0; cc2 < 2; cc2++) {
            const float* tp = st[buf][cc2];
            float t9[9];
            #pragma unroll
            for (int dy = 0; dy < 3; dy++)
                #pragma unroll
                for (int dx = 0; dx < 3; dx++)
                    t9[dy * 3 + dx] = tp[(ty + dy) * 19 + tx + dx];
            const ulonglong2* wq = (const ulonglong2*)wsm[buf][cc2];
            #pragma unroll
            for (int t = 0; t < 9; t++) {
                ull d = dup2(t9[t]);
                ulonglong2 w01 = wq[t * 3], w23 = wq[t * 3 + 1], w45 = wq[t * 3 + 2];
                fma2(acc[0], d, w01.x); fma2(acc[1], d, w01.y);
                fma2(acc[2], d, w23.x); fma2(acc[3], d, w23.y);
                fma2(acc[4], d, w45.x); fma2(acc[5], d, w45.y);
            }
        }
        __syncthreads();
    }

    // stores: vch {0,1,3,4, 7,8,10,11} -> planes 0..7
    int p0 = (oy0 + ty) * W1 + ox0 + tx;
    float2 a0 = up2(acc[0]), a1 = up2(acc[1]), a2 = up2(acc[2]);
    float2 a3 = up2(acc[3]), a4 = up2(acc[4]), a5 = up2(acc[5]);
    float* ob = g_off + (size_t)b * 8 * HW1 + p0;
    ob[0 * (size_t)HW1] = a0.x;  ob[1 * (size_t)HW1] = a0.y;
    ob[2 * (size_t)HW1] = a1.y;  ob[3 * (size_t)HW1] = a2.x;
    ob[4 * (size_t)HW1] = a3.y;  ob[5 * (size_t)HW1] = a4.x;
    ob[6 * (size_t)HW1] = a5.x;  ob[7 * (size_t)HW1] = a5.y;

    // stats: 6 groups = the 6 vch pairs
    int lane = tid & 31;
    #pragma unroll
    for (int gi = 0; gi < 6; gi++) {
        float2 a = up2(acc[gi]);
        float s = a.x + a.y;
        float q = a.x * a.x + a.y * a.y;
        #pragma unroll
        for (int o = 16; o > 0; o >>= 1) {
            s += __shfl_down_sync(0xffffffffu, s, o);
            q += __shfl_down_sync(0xffffffffu, q, o);
        }
        if (lane == 0) {
            atomicAdd(&g_osum[b * 6 + gi], s);
            atomicAdd(&g_osq[b * 6 + gi], q);
        }
    }
}

// ---------------- fused GN+tanh+cum + vec4-gather sample + K-conv + stats (1px/thread) ----------------
__global__ void __launch_bounds__(256) sample_kernel(
        const float* __restrict__ dwx, const float* __restrict__ dbx,
        const float* __restrict__ dwy, const float* __restrict__ dby,
        const float* __restrict__ gxg, const float* __restrict__ gxb,
        const float* __restrict__ gyg, const float* __restrict__ gyb) {
    int bz = blockIdx.y;
    int b = bz >> 1, morph = bz & 1;
    const float* dw = morph ? dwy : dwx;
    const float* db = morph ? dby : dbx;

    __shared__ __align__(16) ull sw2[1280];  // [cg][k][cp][oc]
    __shared__ float sA[4], sB[4];
    int tid = threadIdx.x;
    for (int i = tid; i < 1280; i += 256) {
        int cg = i / 80, r = i - cg * 80;
        int k = r >> 4, r2 = r & 15;
        int cp = r2 >> 3, oc = r2 & 7;
        int c0 = cg * 4 + cp * 2;
        sw2[i] = pk2(dw[oc * 320 + c0 * 5 + k], dw[oc * 320 + (c0 + 1) * 5 + k]);
    }
    if (tid < 4) {
        int gi, ci; float gamma, beta;
        if (morph == 0) {
            const int gtab[4] = {0, 0, 1, 2}; const int ctab[4] = {0, 1, 3, 4};
            gi = b * 6 + gtab[tid]; ci = ctab[tid];
            gamma = gxg[ci]; beta = gxb[ci];
        } else {
            const int gtab[4] = {3, 4, 5, 5}; const int ctab[4] = {5, 6, 8, 9};
            gi = b * 6 + gtab[tid]; ci = ctab[tid];
            gamma = gyg[ci]; beta = gyb[ci];
        }
        float mean = g_osum[gi] * (1.f / 131072.f);
        float var  = g_osq[gi]  * (1.f / 131072.f) - mean * mean;
        float rs = rsqrtf(var + EPSF) * gamma;
        sA[tid] = rs; sB[tid] = beta - mean * rs;
    }
    __syncthreads();

    int pix = blockIdx.x * 256 + tid;        // 0..65535
    int hh = pix >> 8, ww = pix & 255;
    int stride = morph ? 1 : W1;

    int o0[5];
    float wt[5];
    {
        const float* ob = g_off + ((size_t)b * 8 + morph * 4) * HW1 + pix;
        float t0 = tanhf(fmaf(ob[0 * (size_t)HW1], sA[0], sB[0]));
        float t1 = tanhf(fmaf(ob[1 * (size_t)HW1], sA[1], sB[1]));
        float t2 = tanhf(fmaf(ob[2 * (size_t)HW1], sA[2], sB[2]));
        float t3 = tanhf(fmaf(ob[3 * (size_t)HW1], sA[3], sB[3]));
        float cum[5] = {t0 + t1, t1, 0.f, t2, t2 + t3};
        #pragma unroll
        for (int k = 0; k < 5; k++) {
            if (morph == 0) {
                float y = fminf(fmaxf((float)hh + cum[k], 0.f), 255.f);
                float y0 = floorf(y);
                wt[k] = y - y0;
                int xi = min(max(ww + k - 2, 0), 255);
                o0[k] = (int)y0 * W1 + xi;
            } else {
                float xx = fminf(fmaxf((float)ww + cum[k], 0.f), 255.f);
                float x0 = floorf(xx);
                wt[k] = xx - x0;
                int yi = min(max(hh + k - 2, 0), 255);
                o0[k] = yi * W1 + (int)x0;
            }
        }
    }

    ull acc[8];
    #pragma unroll
    for (int oc = 0; oc < 8; oc++) acc[oc] = 0ull;

    const float4* hp = (const float4*)g_h4 + (size_t)b * 16 * HW1;
    #pragma unroll 1
    for (int cg = 0; cg < 16; cg++) {
        const ulonglong2* wq = (const ulonglong2*)sw2 + cg * 40;
        #pragma unroll
        for (int k = 0; k < 5; k++) {
            float4 A = __ldg(hp + o0[k]);
            ull v01, v23;
            if (k == 2) {
                v01 = pk2(A.x, A.y);
                v23 = pk2(A.z, A.w);
            } else {
                float4 Bv = __ldg(hp + o0[k] + stride);
                ull w2d = dup2(wt[k]);
                v01 = pk2(A.x, A.y); v23 = pk2(A.z, A.w);
                ull d01 = sub2(pk2(Bv.x, Bv.y), v01);
                ull d23 = sub2(pk2(Bv.z, Bv.w), v23);
                fma2(v01, w2d, d01);
                fma2(v23, w2d, d23);
            }
            #pragma unroll
            for (int q = 0; q < 4; q++) {
                ulonglong2 wA = wq[k * 8 + q];
                ulonglong2 wB = wq[k * 8 + 4 + q];
                fma2(acc[2 * q],     v01, wA.x);
                fma2(acc[2 * q + 1], v01, wA.y);
                fma2(acc[2 * q],     v23, wB.x);
                fma2(acc[2 * q + 1], v23, wB.y);
            }
        }
        hp += HW1;
    }

    float* op = g_outraw + ((size_t)b * 16 + morph * 8) * HW1 + pix;
    float rr[8];
    #pragma unroll
    for (int oc = 0; oc < 8; oc++) {
        float2 t = up2(acc[oc]);
        float r = t.x + t.y + __ldg(db + oc);
        rr[oc] = r;
        op[(size_t)oc * HW1] = r;
    }

    int lane = tid & 31;
    #pragma unroll
    for (int gi = 0; gi < 2; gi++) {
        float s = 0.f, q = 0.f;
        #pragma unroll
        for (int oc = 4 * gi; oc < 4 * gi + 4; oc++) {
            s += rr[oc];
            q = fmaf(rr[oc], rr[oc], q);
        }
        #pragma unroll
        for (int o = 16; o > 0; o >>= 1) {
            s += __shfl_down_sync(0xffffffffu, s, o);
            q += __shfl_down_sync(0xffffffffu, q, o);
        }
        if (lane == 0) {
            atomicAdd(&g_ssum[b * 4 + morph * 2 + gi], s);
            atomicAdd(&g_ssq[b * 4 + morph * 2 + gi], q);
        }
    }
}

// ---------------- GN+ReLU + concat + 1x1 conv (16->64) + BN + ReLU ----------------
__global__ void __launch_bounds__(256) final_kernel(
        const float* __restrict__ gx_g, const float* __restrict__ gx_b,
        const float* __restrict__ gy_g, const float* __restrict__ gy_b,
        const float* __restrict__ w2,
        const float* __restrict__ bn2g, const float* __restrict__ bn2b,
        const float* __restrict__ bn2m, const float* __restrict__ bn2v,
        float* __restrict__ out) {
    __shared__ __align__(16) ull swt[16 * 32];
    __shared__ ull scp[32], shp[32];
    __shared__ float gnA[16], gnB[16];
    int tid = threadIdx.x;
    int idx = blockIdx.x * 256 + tid;
    int b = idx >> 16, p = idx & 65535;

    for (int i = tid; i < 512; i += 256) {
        int ch = i >> 5, op = i & 31;
        swt[i] = pk2(w2[(2 * op) * 16 + ch], w2[(2 * op + 1) * 16 + ch]);
    }
    if (tid < 32) {
        int oc0 = 2 * tid, oc1 = 2 * tid + 1;
        float sc0 = bn2g[oc0] * rsqrtf(bn2v[oc0] + EPSF);
        float sc1 = bn2g[oc1] * rsqrtf(bn2v[oc1] + EPSF);
        scp[tid] = pk2(sc0, sc1);
        shp[tid] = pk2(bn2b[oc0] - bn2m[oc0] * sc0, bn2b[oc1] - bn2m[oc1] * sc1);
    }
    if (tid < 16) {
        int ch = tid;
        int gi = b * 4 + ch / 4;
        float mean = g_ssum[gi] * (1.f / 262144.f);
        float var  = g_ssq[gi]  * (1.f / 262144.f) - mean * mean;
        float rs = rsqrtf(var + EPSF);
        float gamma = (ch < 8) ? gx_g[ch] : gy_g[ch - 8];
        float beta  = (ch < 8) ? gx_b[ch] : gy_b[ch - 8];
        gnA[ch] = rs * gamma; gnB[ch] = beta - mean * rs * gamma;
    }
    __syncthreads();

    ull catd[16];
    #pragma unroll
    for (int ch = 0; ch < 16; ch++) {
        float val = g_outraw[((size_t)b * 16 + ch) * HW1 + p];
        val = fmaxf(fmaf(val, gnA[ch], gnB[ch]), 0.f);
        catd[ch] = dup2(val);
    }

    ull acc[32];
    #pragma unroll
    for (int i = 0; i < 32; i++) acc[i] = 0ull;
    #pragma unroll
    for (int ch = 0; ch < 16; ch++) {
        const ulonglong2* wrow = (const ulonglong2*)(swt + ch * 32);
        #pragma unroll
        for (int op2 = 0; op2 < 16; op2++) {
            ulonglong2 ww = wrow[op2];
            fma2(acc[2 * op2], catd[ch], ww.x);
            fma2(acc[2 * op2 + 1], catd[ch], ww.y);
        }
    }

    float* obp = out + (size_t)b * 64 * HW1 + p;
    #pragma unroll
    for (int op = 0; op < 32; op++) {
        ull tmp = shp[op];
        fma2(tmp, acc[op], scp[op]);
        float2 vv = up2(tmp);
        obp[(size_t)(2 * op) * HW1]     = fmaxf(vv.x, 0.f);
        obp[(size_t)(2 * op + 1) * HW1] = fmaxf(vv.y, 0.f);
    }
}

// ---------------- launch ----------------
extern "C" void kernel_launch(void* const* d_in, const int* in_sizes, int n_in,
                              void* d_out, int out_size) {
    const float* x        = (const float*)d_in[0];
    const float* conv1_w  = (const float*)d_in[1];
    const float* bn1_g    = (const float*)d_in[2];
    const float* bn1_b    = (const float*)d_in[3];
    const float* bn1_m    = (const float*)d_in[4];
    const float* bn1_v    = (const float*)d_in[5];
    const float* offx_w   = (const float*)d_in[6];
    const float* offx_b   = (const float*)d_in[7];
    const float* gnoffx_g = (const float*)d_in[8];
    const float* gnoffx_b = (const float*)d_in[9];
    const float* dscx_w   = (const float*)d_in[10];
    const float* dscx_b   = (const float*)d_in[11];
    const float* gnx_g    = (const float*)d_in[12];
    const float* gnx_b    = (const float*)d_in[13];
    const float* offy_w   = (const float*)d_in[14];
    const float* offy_b   = (const float*)d_in[15];
    const float* gnoffy_g = (const float*)d_in[16];
    const float* gnoffy_b = (const float*)d_in[17];
    const float* dscy_w   = (const float*)d_in[18];
    const float* dscy_b   = (const float*)d_in[19];
    const float* gny_g    = (const float*)d_in[20];
    const float* gny_b    = (const float*)d_in[21];
    const float* conv2_w  = (const float*)d_in[22];
    const float* bn2_g    = (const float*)d_in[23];
    const float* bn2_b    = (const float*)d_in[24];
    const float* bn2_m    = (const float*)d_in[25];
    const float* bn2_v    = (const float*)d_in[26];
    float* out = (float*)d_out;

    prep_kernel<<<14, 256>>>(offx_w, offy_w);
    conv1_kernel<<<512, 256>>>(x, conv1_w, bn1_g, bn1_b, bn1_m, bn1_v);
    offconv_kernel<<<dim3(16, 16, 2), 256>>>(offx_b, offy_b);
    sample_kernel<<<dim3(256, 4), 256>>>(dscx_w, dscx_b, dscy_w, dscy_b,
                                         gnoffx_g, gnoffx_b, gnoffy_g, gnoffy_b);
    final_kernel<<<512, 256>>>(gnx_g, gnx_b, gny_g, gny_b, conv2_w,
                               bn2_g, bn2_b, bn2_m, bn2_v, out);
}

// round 8
// speedup vs baseline: 1.2451x; 1.2451x over previous
#include <cuda_runtime.h>
#include <math.h>

#define H1 256
#define W1 256
#define HW1 65536
#define EPSF 1e-5f

typedef unsigned long long ull;
typedef unsigned int u32;

__device__ __forceinline__ ull pk2(float a, float b) {
    ull r; asm("mov.b64 %0,{%1,%2};" : "=l"(r) : "f"(a), "f"(b)); return r;
}
__device__ __forceinline__ ull dup2(float a) {
    ull r; asm("mov.b64 %0,{%1,%1};" : "=l"(r) : "f"(a)); return r;
}
__device__ __forceinline__ void fma2(ull& d, ull a, ull b) {
    asm("fma.rn.f32x2 %0,%1,%2,%0;" : "+l"(d) : "l"(a), "l"(b));
}
__device__ __forceinline__ ull sub2(ull a, ull b) {
    ull r; asm("sub.rn.f32x2 %0,%1,%2;" : "=l"(r) : "l"(a), "l"(b)); return r;
}
__device__ __forceinline__ float2 up2(ull u) {
    float2 r; asm("mov.b64 {%0,%1},%2;" : "=f"(r.x), "=f"(r.y) : "l"(u)); return r;
}
__device__ __forceinline__ u32 s2u(const void* p) {
    u32 a; asm("{.reg .u64 t; cvta.to.shared.u64 t, %1; cvt.u32.u64 %0, t;}" : "=r"(a) : "l"(p));
    return a;
}
__device__ __forceinline__ void cp4(u32 dst, const void* src, int sz) {
    asm volatile("cp.async.ca.shared.global [%0], [%1], 4, %2;" :: "r"(dst), "l"(src), "r"(sz));
}
__device__ __forceinline__ void cp16(u32 dst, const void* src) {
    asm volatile("cp.async.cg.shared.global [%0], [%1], 16;" :: "r"(dst), "l"(src));
}
__device__ __forceinline__ void cp_commit() {
    asm volatile("cp.async.commit_group;");
}
template<int N> __device__ __forceinline__ void cp_wait() {
    asm volatile("cp.async.wait_group %0;" :: "n"(N));
}

// ---------------- scratch ----------------
__device__ float g_h[2 * 64 * HW1];                       // planar (offconv)
__device__ float g_h4[1024 + 2 * 64 * HW1 + 1024];        // front pad + [b][c/4][p][4] + rear pad
__device__ float g_off[2 * 8 * HW1];
__device__ float g_outraw[2 * 16 * HW1];
__device__ __align__(16) ull g_woff[64 * 12 * 12];        // dup'd offconv weights [c][vch][12]
__device__ float g_osum[12], g_osq[12];
__device__ float g_ssum[8],  g_ssq[8];

// ---------------- prep ----------------
__global__ void prep_kernel(const float* __restrict__ wx, const float* __restrict__ wy) {
    int idx = blockIdx.x * 256 + threadIdx.x;
    if (idx < 12) { g_osum[idx] = 0.f; g_osq[idx] = 0.f; }
    if (idx < 8)  { g_ssum[idx] = 0.f; g_ssq[idx] = 0.f; }
    if (idx < 1024) {
        g_h4[idx] = 0.f;
        g_h4[1024 + 2 * 64 * HW1 + idx] = 0.f;
    }
    if (idx < 9216) {
        int c = idx / 144, rem = idx - c * 144;
        int vch = rem / 12, t = rem - vch * 12;
        float val = 0.f;
        if (t < 9)
            val = (vch < 6) ? wx[vch * 576 + c * 9 + t]
                            : wy[(vch - 2) * 576 + c * 9 + t];
        g_woff[idx] = dup2(val);
    }
}

// ---------------- conv1 3x3 s2 pad1 (3->64) + BN + ReLU; dual-layout store ----------------
__global__ void __launch_bounds__(256) conv1_kernel(
        const float* __restrict__ x, const float* __restrict__ w,
        const float* __restrict__ g, const float* __restrict__ bb,
        const float* __restrict__ m, const float* __restrict__ v) {
    __shared__ __align__(16) ull swp[864];
    __shared__ float ssc[64], ssh[64];
    int tid = threadIdx.x;
    for (int i = tid; i < 864; i += 256) {
        int t = i >> 5, op = i & 31;
        swp[i] = pk2(w[(2 * op) * 27 + t], w[(2 * op + 1) * 27 + t]);
    }
    if (tid < 64) {
        float sc = g[tid] * rsqrtf(v[tid] + EPSF);
        ssc[tid] = sc; ssh[tid] = bb[tid] - m[tid] * sc;
    }
    __syncthreads();

    int idx = blockIdx.x * 256 + tid;
    int b = idx >> 16, p = idx & 65535;
    int oy = p >> 8, ox = p & 255;
    const float* xb = x + (size_t)b * 3 * 512 * 512;

    ull pd[27];
    #pragma unroll
    for (int ic = 0; ic < 3; ic++)
        #pragma unroll
        for (int dy = 0; dy < 3; dy++) {
            int iy = 2 * oy - 1 + dy;
            #pragma unroll
            for (int dx = 0; dx < 3; dx++) {
                int ix = 2 * ox - 1 + dx;
                float val = 0.f;
                if (iy >= 0 && ix >= 0) val = xb[(ic * 512 + iy) * 512 + ix];
                pd[ic * 9 + dy * 3 + dx] = dup2(val);
            }
        }

    float* hb = g_h + (size_t)b * 64 * HW1 + p;
    float4* hb4 = (float4*)g_h4 + 64 + (size_t)b * 16 * HW1 + p;
    #pragma unroll 1
    for (int half = 0; half < 2; half++) {
        ull acc[16];
        #pragma unroll
        for (int j = 0; j < 16; j++) acc[j] = 0ull;
        #pragma unroll
        for (int t = 0; t < 27; t++)
            #pragma unroll
            for (int j = 0; j < 16; j++)
                fma2(acc[j], pd[t], swp[t * 32 + half * 16 + j]);
        #pragma unroll
        for (int mm = 0; mm < 8; mm++) {
            int oc = (half * 8 + mm) * 4;
            float2 v0 = up2(acc[2 * mm]);
            float2 v1 = up2(acc[2 * mm + 1]);
            float r0 = fmaxf(fmaf(v0.x, ssc[oc],     ssh[oc]),     0.f);
            float r1 = fmaxf(fmaf(v0.y, ssc[oc + 1], ssh[oc + 1]), 0.f);
            float r2 = fmaxf(fmaf(v1.x, ssc[oc + 2], ssh[oc + 2]), 0.f);
            float r3 = fmaxf(fmaf(v1.y, ssc[oc + 3], ssh[oc + 3]), 0.f);
            hb[(size_t)oc * HW1]       = r0;
            hb[(size_t)(oc + 1) * HW1] = r1;
            hb[(size_t)(oc + 2) * HW1] = r2;
            hb[(size_t)(oc + 3) * HW1] = r3;
            hb4[(size_t)(half * 8 + mm) * HW1] = make_float4(r0, r1, r2, r3);
        }
    }
}

// ---------------- offset convs: 12 needed channels, cp.async pipelined (round-6) ----------------
#define OTW 35
#define OTR 18
#define OTS (OTR * OTW)
__global__ void __launch_bounds__(256) offconv_kernel(
        const float* __restrict__ bxp, const float* __restrict__ byp) {
    __shared__ float st[2][2][OTS];
    __shared__ __align__(16) ull wsm[2][2][144];
    __shared__ float sbias[12];
    int tid = threadIdx.x, tx = tid & 31, tyy = tid >> 5;
    int b = blockIdx.z;
    int ox0 = blockIdx.x * 32, oy0 = blockIdx.y * 16;

    if (tid < 12) sbias[tid] = (tid < 6) ? bxp[tid] : byp[tid - 2];

    int fe[5], fsrc[5], fch[5], fsz[5];
    #pragma unroll
    for (int s = 0; s < 5; s++) {
        int i = tid + s * 256;
        int valid = (i < 1260);
        int ii = valid ? i : 0;
        int ch = (ii >= OTS) ? 1 : 0;
        int j = ii - ch * OTS;
        int r = j / OTW, cc = j - r * OTW;
        int gy = oy0 - 1 + r, gx = ox0 - 1 + cc;
        int ok = valid && gy >= 0 && gy < H1 && gx >= 0 && gx < W1 && cc < 34;
        fe[s] = ch * OTS + j;
        fch[s] = ch;
        fsrc[s] = min(max(gy, 0), 255) * W1 + min(max(gx, 0), 255);
        fsz[s] = ok ? 4 : 0;
        if (!valid) fsz[s] = -1;
    }
    u32 st0 = s2u(&st[0][0][0]), st1 = s2u(&st[1][0][0]);
    u32 ws0 = s2u(&wsm[0][0][0]), ws1 = s2u(&wsm[1][0][0]);
    const float* hb = g_h + (size_t)b * 64 * HW1;
    const char* wgp = (const char*)g_woff;

    __syncthreads();
    ull acc[12];
    #pragma unroll
    for (int i = 0; i < 12; i++) acc[i] = dup2(sbias[i]);

    {
        #pragma unroll
        for (int s = 0; s < 5; s++)
            if (fsz[s] >= 0) cp4(st0 + fe[s] * 4, hb + (size_t)fch[s] * HW1 + fsrc[s], fsz[s]);
        if (tid < 144) {
            int chi = tid >= 72 ? 1 : 0, o = tid - chi * 72;
            cp16(ws0 + (chi * 144 + o * 2) * 8, wgp + ((size_t)chi * 72 + o) * 16);
        }
        cp_commit();
    }

    #pragma unroll 1
    for (int sg = 0; sg < 32; sg++) {
        int buf = sg & 1;
        if (sg + 1 < 32) {
            u32 std = buf ? st0 : st1;
            u32 wsd = buf ? ws0 : ws1;
            int cbase = 2 * (sg + 1);
            #pragma unroll
            for (int s = 0; s < 5; s++)
                if (fsz[s] >= 0) cp4(std + fe[s] * 4, hb + (size_t)(cbase + fch[s]) * HW1 + fsrc[s], fsz[s]);
            if (tid < 144) {
                int chi = tid >= 72 ? 1 : 0, o = tid - chi * 72;
                cp16(wsd + (chi * 144 + o * 2) * 8, wgp + ((size_t)(cbase + chi) * 72 + o) * 16);
            }
            cp_commit();
            cp_wait<1>();
        } else {
            cp_wait<0>();
        }
        __syncthreads();

        #pragma unroll
        for (int cc2 = 0; cc2 < 2; cc2++) {
            const float* tp = st[buf][cc2];
            ull pk[9];
            #pragma unroll
            for (int dy = 0; dy < 3; dy++)
                #pragma unroll
                for (int dx = 0; dx < 3; dx++)
                    pk[dy * 3 + dx] = pk2(tp[(tyy + dy) * OTW + tx + dx],
                                          tp[(tyy + 8 + dy) * OTW + tx + dx]);
            const ull* wc = wsm[buf][cc2];
            #pragma unroll
            for (int vch = 0; vch < 12; vch++) {
                const ulonglong2* wp = (const ulonglong2*)(wc + vch * 12);
                ulonglong2 w01 = wp[0], w23 = wp[1], w45 = wp[2], w67 = wp[3];
                ull w8 = wc[vch * 12 + 8];
                fma2(acc[vch], pk[0], w01.x); fma2(acc[vch], pk[1], w01.y);
                fma2(acc[vch], pk[2], w23.x); fma2(acc[vch], pk[3], w23.y);
                fma2(acc[vch], pk[4], w45.x); fma2(acc[vch], pk[5], w45.y);
                fma2(acc[vch], pk[6], w67.x); fma2(acc[vch], pk[7], w67.y);
                fma2(acc[vch], pk[8], w8);
            }
        }
        __syncthreads();
    }

    int p0 = (oy0 + tyy) * W1 + ox0 + tx;
    int p1 = p0 + 8 * W1;
    const int chs[8] = {0, 1, 3, 4, 7, 8, 10, 11};
    float* ob = g_off + (size_t)b * 8 * HW1;
    #pragma unroll
    for (int s = 0; s < 8; s++) {
        float2 vv = up2(acc[chs[s]]);
        ob[(size_t)s * HW1 + p0] = vv.x;
        ob[(size_t)s * HW1 + p1] = vv.y;
    }

    int lane = tid & 31;
    #pragma unroll
    for (int gi = 0; gi < 6; gi++) {
        float2 a = up2(acc[2 * gi]), c2 = up2(acc[2 * gi + 1]);
        float s = a.x + a.y + c2.x + c2.y;
        float q = a.x * a.x + a.y * a.y + c2.x * c2.x + c2.y * c2.y;
        #pragma unroll
        for (int o = 16; o > 0; o >>= 1) {
            s += __shfl_down_sync(0xffffffffu, s, o);
            q += __shfl_down_sync(0xffffffffu, q, o);
        }
        if (lane == 0) {
            atomicAdd(&g_osum[b * 6 + gi], s);
            atomicAdd(&g_osq[b * 6 + gi], q);
        }
    }
}

// ---------------- smem-tiled sampler: GN+tanh+cum + bilinear + K-conv + stats ----------------
// Tile 32x16 px, 2 px/thread (rows ty, ty+8). Halo 21 rows x 40 float4-cells per cg,
// filled by cp.async 16B from vec4 layout; taps are LDS.128 from the tile.
#define SROWS 21
#define SCOLS 40
#define SCELLS (SROWS * SCOLS)      // 840
#define STILEB (SCELLS * 16)        // bytes per buffer
__global__ void __launch_bounds__(256) sample_kernel(
        const float* __restrict__ dwx, const float* __restrict__ dbx,
        const float* __restrict__ dwy, const float* __restrict__ dby,
        const float* __restrict__ gxg, const float* __restrict__ gxb,
        const float* __restrict__ gyg, const float* __restrict__ gyb) {
    int bz = blockIdx.z;
    int b = bz >> 1, morph = bz & 1;
    const float* dw = morph ? dwy : dwx;
    const float* db = morph ? dby : dbx;

    __shared__ __align__(16) float4 tile[2][SCELLS];
    __shared__ __align__(16) ull sw2[1280];  // [cg][k][cp][oc]
    __shared__ float sA[4], sB[4];
    int tid = threadIdx.x, tx = tid & 31, ty = tid >> 5;
    int ox0 = blockIdx.x * 32, oy0 = blockIdx.y * 16;

    for (int i = tid; i < 1280; i += 256) {
        int cg = i / 80, r = i - cg * 80;
        int k = r >> 4, r2 = r & 15;
        int cp = r2 >> 3, oc = r2 & 7;
        int c0 = cg * 4 + cp * 2;
        sw2[i] = pk2(dw[oc * 320 + c0 * 5 + k], dw[oc * 320 + (c0 + 1) * 5 + k]);
    }
    if (tid < 4) {
        int gi, ci; float gamma, beta;
        if (morph == 0) {
            const int gtab[4] = {0, 0, 1, 2}; const int ctab[4] = {0, 1, 3, 4};
            gi = b * 6 + gtab[tid]; ci = ctab[tid];
            gamma = gxg[ci]; beta = gxb[ci];
        } else {
            const int gtab[4] = {3, 4, 5, 5}; const int ctab[4] = {5, 6, 8, 9};
            gi = b * 6 + gtab[tid]; ci = ctab[tid];
            gamma = gyg[ci]; beta = gyb[ci];
        }
        float mean = g_osum[gi] * (1.f / 131072.f);
        float var  = g_osq[gi]  * (1.f / 131072.f) - mean * mean;
        float rs = rsqrtf(var + EPSF) * gamma;
        sA[tid] = rs; sB[tid] = beta - mean * rs;
    }

    // fill slots: 840 float4 cells, 4 slots/thread
    int soff[4]; u32 sdst[4];
    #pragma unroll
    for (int s = 0; s < 4; s++) {
        int i = tid + s * 256;
        if (i < SCELLS) {
            int r = i / SCOLS, c4 = i - r * SCOLS;
            int gy = min(max(oy0 - 2 + r, 0), 255);
            soff[s] = gy * 256 + ox0 - 4 + c4;
            sdst[s] = s2u(&tile[0][0]) + i * 16;
        } else {
            soff[s] = 1 << 30;
        }
    }
    const float4* g4 = (const float4*)g_h4 + 64 + (size_t)b * 16 * HW1;
    int step = morph ? 1 : SCOLS;

    __syncthreads();

    // per-pixel taps as tile-cell offsets
    int o0[2][5];
    float wt[2][5];
    #pragma unroll
    for (int j = 0; j < 2; j++) {
        int yy = oy0 + ty + 8 * j;
        int ww = ox0 + tx;
        int p = yy * W1 + ww;
        const float* ob = g_off + ((size_t)b * 8 + morph * 4) * HW1 + p;
        float t0 = tanhf(fmaf(ob[0 * (size_t)HW1], sA[0], sB[0]));
        float t1 = tanhf(fmaf(ob[1 * (size_t)HW1], sA[1], sB[1]));
        float t2 = tanhf(fmaf(ob[2 * (size_t)HW1], sA[2], sB[2]));
        float t3 = tanhf(fmaf(ob[3 * (size_t)HW1], sA[3], sB[3]));
        float cum[5] = {t0 + t1, t1, 0.f, t2, t2 + t3};
        #pragma unroll
        for (int k = 0; k < 5; k++) {
            if (morph == 0) {
                float y = fminf(fmaxf((float)yy + cum[k], 0.f), 255.f);
                float y0 = floorf(y);
                wt[j][k] = y - y0;
                int xi = min(max(ox0 + tx + k - 2, 0), 255);
                o0[j][k] = ((int)y0 - oy0 + 2) * SCOLS + (xi - ox0 + 4);
            } else {
                float xx = fminf(fmaxf((float)(ox0 + tx) + cum[k], 0.f), 255.f);
                float x0 = floorf(xx);
                wt[j][k] = xx - x0;
                int yi = min(max(yy + k - 2, 0), 255);
                o0[j][k] = (yi - oy0 + 2) * SCOLS + ((int)x0 - ox0 + 4);
            }
        }
    }

    ull acc[2][8];
    #pragma unroll
    for (int j = 0; j < 2; j++)
        #pragma unroll
        for (int oc = 0; oc < 8; oc++) acc[j][oc] = 0ull;

    // issue fill for cg 0
    {
        #pragma unroll
        for (int s = 0; s < 4; s++)
            if (soff[s] < (1 << 29)) cp16(sdst[s], g4 + soff[s]);
        cp_commit();
    }

    #pragma unroll 1
    for (int cg = 0; cg < 16; cg++) {
        int buf = cg & 1;
        if (cg + 1 < 16) {
            u32 boff = (buf ^ 1) * STILEB;
            const float4* gsrc = g4 + (size_t)(cg + 1) * HW1;
            #pragma unroll
            for (int s = 0; s < 4; s++)
                if (soff[s] < (1 << 29)) cp16(sdst[s] + boff, gsrc + soff[s]);
            cp_commit();
            cp_wait<1>();
        } else {
            cp_wait<0>();
        }
        __syncthreads();

        const float4* tp = tile[buf];
        const ulonglong2* wq = (const ulonglong2*)sw2 + cg * 40;
        #pragma unroll
        for (int k = 0; k < 5; k++) {
            ull v01[2], v23[2];
            #pragma unroll
            for (int j = 0; j < 2; j++) {
                float4 A = tp[o0[j][k]];
                if (k == 2) {
                    v01[j] = pk2(A.x, A.y);
                    v23[j] = pk2(A.z, A.w);
                } else {
                    float4 Bv = tp[o0[j][k] + step];
                    ull w2d = dup2(wt[j][k]);
                    ull a01 = pk2(A.x, A.y), a23 = pk2(A.z, A.w);
                    ull d01 = sub2(pk2(Bv.x, Bv.y), a01);
                    ull d23 = sub2(pk2(Bv.z, Bv.w), a23);
                    fma2(a01, w2d, d01);
                    fma2(a23, w2d, d23);
                    v01[j] = a01; v23[j] = a23;
                }
            }
            #pragma unroll
            for (int q = 0; q < 4; q++) {
                ulonglong2 wA = wq[k * 8 + q];
                ulonglong2 wB = wq[k * 8 + 4 + q];
                #pragma unroll
                for (int j = 0; j < 2; j++) {
                    fma2(acc[j][2 * q],     v01[j], wA.x);
                    fma2(acc[j][2 * q + 1], v01[j], wA.y);
                    fma2(acc[j][2 * q],     v23[j], wB.x);
                    fma2(acc[j][2 * q + 1], v23[j], wB.y);
                }
            }
        }
        __syncthreads();
    }

    float* op = g_outraw + ((size_t)b * 16 + morph * 8) * HW1;
    float rr[2][8];
    #pragma unroll
    for (int j = 0; j < 2; j++) {
        int p = (oy0 + ty + 8 * j) * W1 + ox0 + tx;
        #pragma unroll
        for (int oc = 0; oc < 8; oc++) {
            float2 t = up2(acc[j][oc]);
            float r = t.x + t.y + __ldg(db + oc);
            rr[j][oc] = r;
            op[(size_t)oc * HW1 + p] = r;
        }
    }

    int lane = tid & 31;
    #pragma unroll
    for (int gi = 0; gi < 2; gi++) {
        float s = 0.f, q = 0.f;
        #pragma unroll
        for (int j = 0; j < 2; j++)
            #pragma unroll
            for (int oc = 4 * gi; oc < 4 * gi + 4; oc++) {
                s += rr[j][oc];
                q = fmaf(rr[j][oc], rr[j][oc], q);
            }
        #pragma unroll
        for (int o = 16; o > 0; o >>= 1) {
            s += __shfl_down_sync(0xffffffffu, s, o);
            q += __shfl_down_sync(0xffffffffu, q, o);
        }
        if (lane == 0) {
            atomicAdd(&g_ssum[b * 4 + morph * 2 + gi], s);
            atomicAdd(&g_ssq[b * 4 + morph * 2 + gi], q);
        }
    }
}

// ---------------- GN+ReLU + concat + 1x1 conv (16->64) + BN + ReLU ----------------
__global__ void __launch_bounds__(256) final_kernel(
        const float* __restrict__ gx_g, const float* __restrict__ gx_b,
        const float* __restrict__ gy_g, const float* __restrict__ gy_b,
        const float* __restrict__ w2,
        const float* __restrict__ bn2g, const float* __restrict__ bn2b,
        const float* __restrict__ bn2m, const float* __restrict__ bn2v,
        float* __restrict__ out) {
    __shared__ __align__(16) ull swt[16 * 32];
    __shared__ ull scp[32], shp[32];
    __shared__ float gnA[16], gnB[16];
    int tid = threadIdx.x;
    int idx = blockIdx.x * 256 + tid;
    int b = idx >> 16, p = idx & 65535;

    for (int i = tid; i < 512; i += 256) {
        int ch = i >> 5, op = i & 31;
        swt[i] = pk2(w2[(2 * op) * 16 + ch], w2[(2 * op + 1) * 16 + ch]);
    }
    if (tid < 32) {
        int oc0 = 2 * tid, oc1 = 2 * tid + 1;
        float sc0 = bn2g[oc0] * rsqrtf(bn2v[oc0] + EPSF);
        float sc1 = bn2g[oc1] * rsqrtf(bn2v[oc1] + EPSF);
        scp[tid] = pk2(sc0, sc1);
        shp[tid] = pk2(bn2b[oc0] - bn2m[oc0] * sc0, bn2b[oc1] - bn2m[oc1] * sc1);
    }
    if (tid < 16) {
        int ch = tid;
        int gi = b * 4 + ch / 4;
        float mean = g_ssum[gi] * (1.f / 262144.f);
        float var  = g_ssq[gi]  * (1.f / 262144.f) - mean * mean;
        float rs = rsqrtf(var + EPSF);
        float gamma = (ch < 8) ? gx_g[ch] : gy_g[ch - 8];
        float beta  = (ch < 8) ? gx_b[ch] : gy_b[ch - 8];
        gnA[ch] = rs * gamma; gnB[ch] = beta - mean * rs * gamma;
    }
    __syncthreads();

    ull catd[16];
    #pragma unroll
    for (int ch = 0; ch < 16; ch++) {
        float val = g_outraw[((size_t)b * 16 + ch) * HW1 + p];
        val = fmaxf(fmaf(val, gnA[ch], gnB[ch]), 0.f);
        catd[ch] = dup2(val);
    }

    ull acc[32];
    #pragma unroll
    for (int i = 0; i < 32; i++) acc[i] = 0ull;
    #pragma unroll
    for (int ch = 0; ch < 16; ch++) {
        const ulonglong2* wrow = (const ulonglong2*)(swt + ch * 32);
        #pragma unroll
        for (int op2 = 0; op2 < 16; op2++) {
            ulonglong2 ww = wrow[op2];
            fma2(acc[2 * op2], catd[ch], ww.x);
            fma2(acc[2 * op2 + 1], catd[ch], ww.y);
        }
    }

    float* obp = out + (size_t)b * 64 * HW1 + p;
    #pragma unroll
    for (int op = 0; op < 32; op++) {
        ull tmp = shp[op];
        fma2(tmp, acc[op], scp[op]);
        float2 vv = up2(tmp);
        obp[(size_t)(2 * op) * HW1]     = fmaxf(vv.x, 0.f);
        obp[(size_t)(2 * op + 1) * HW1] = fmaxf(vv.y, 0.f);
    }
}

// ---------------- launch ----------------
extern "C" void kernel_launch(void* const* d_in, const int* in_sizes, int n_in,
                              void* d_out, int out_size) {
    const float* x        = (const float*)d_in[0];
    const float* conv1_w  = (const float*)d_in[1];
    const float* bn1_g    = (const float*)d_in[2];
    const float* bn1_b    = (const float*)d_in[3];
    const float* bn1_m    = (const float*)d_in[4];
    const float* bn1_v    = (const float*)d_in[5];
    const float* offx_w   = (const float*)d_in[6];
    const float* offx_b   = (const float*)d_in[7];
    const float* gnoffx_g = (const float*)d_in[8];
    const float* gnoffx_b = (const float*)d_in[9];
    const float* dscx_w   = (const float*)d_in[10];
    const float* dscx_b   = (const float*)d_in[11];
    const float* gnx_g    = (const float*)d_in[12];
    const float* gnx_b    = (const float*)d_in[13];
    const float* offy_w   = (const float*)d_in[14];
    const float* offy_b   = (const float*)d_in[15];
    const float* gnoffy_g = (const float*)d_in[16];
    const float* gnoffy_b = (const float*)d_in[17];
    const float* dscy_w   = (const float*)d_in[18];
    const float* dscy_b   = (const float*)d_in[19];
    const float* gny_g    = (const float*)d_in[20];
    const float* gny_b    = (const float*)d_in[21];
    const float* conv2_w  = (const float*)d_in[22];
    const float* bn2_g    = (const float*)d_in[23];
    const float* bn2_b    = (const float*)d_in[24];
    const float* bn2_m    = (const float*)d_in[25];
    const float* bn2_v    = (const float*)d_in[26];
    float* out = (float*)d_out;

    prep_kernel<<<36, 256>>>(offx_w, offy_w);
    conv1_kernel<<<512, 256>>>(x, conv1_w, bn1_g, bn1_b, bn1_m, bn1_v);
    offconv_kernel<<<dim3(8, 16, 2), 256>>>(offx_b, offy_b);
    sample_kernel<<<dim3(8, 16, 4), 256>>>(dscx_w, dscx_b, dscy_w, dscy_b,
                                           gnoffx_g, gnoffx_b, gnoffy_g, gnoffy_b);
    final_kernel<<<512, 256>>>(gnx_g, gnx_b, gny_g, gny_b, conv2_w,
                               bn2_g, bn2_b, bn2_m, bn2_v, out);
}